// round 10
// baseline (speedup 1.0000x reference)
#include <cuda_runtime.h>
#include <cuda_bf16.h>

// Problem constants: nw_out is [N=4, C=19, H=512, W=1024] float32.
#define NCH    19
#define NBAT   4
#define HH     512
#define WW     1024
#define HWP    (HH * WW)            // 524288 pixels per image
#define HWP2   (HWP / 2)            // 262144 float2 pairs per image-channel
#define NPIX   (NBAT * HWP)         // 2097152
#define NPAIR  (NPIX / 2)           // 1048576
#define IW_F   0.2f
#define BLOCK_T     128
#define GRID_BLOCKS 592             // 4 CTAs/SM x 148 SMs = one wave at 128 regs

// Scratch accumulators. Zeroed at module load; fused finalize re-zeroes them.
__device__ float        g_sum[NCH] = {};
__device__ unsigned int g_cnt[NCH] = {};
__device__ unsigned int g_done     = 0;

__global__ __launch_bounds__(BLOCK_T, 4) void msiw_kernel(const float2* __restrict__ x2,
                                                          float* __restrict__ out) {
    __shared__ float        s_sum[NCH];
    __shared__ unsigned int s_cnt[NCH];
    const int t = threadIdx.x;
    if (t < NCH) { s_sum[t] = 0.0f; s_cnt[t] = 0u; }
    __syncthreads();

    const int stride = GRID_BLOCKS * BLOCK_T;      // in float2 pairs

    int q = blockIdx.x * BLOCK_T + t;              // always < NPAIR (75776 < 1048576)

    // ---- software pipeline: v = current values, w = prefetched next ----
    float2 v[NCH];
    {
        const int n   = q / HWP2;
        const int hw2 = q - n * HWP2;
        const float2* base = x2 + (size_t)n * (NCH * HWP2) + hw2;
#pragma unroll
        for (int c = 0; c < NCH; c++) v[c] = base[(size_t)c * HWP2];
    }

    while (q < NPAIR) {
        const int qn = q + stride;

        // Prefetch next iteration's 19 channels. These registers are live
        // across the ENTIRE compute phase below (consumed next iteration),
        // so ptxas must keep all 19 LDG.64 in flight while we compute ->
        // continuous ~4.9KB/warp in flight, no barriers, no smem.
        float2 w[NCH];
        if (qn < NPAIR) {
            const int n   = qn / HWP2;
            const int hw2 = qn - n * HWP2;
            const float2* base = x2 + (size_t)n * (NCH * HWP2) + hw2;
#pragma unroll
            for (int c = 0; c < NCH; c++) w[c] = base[(size_t)c * HWP2];
        }

        // ---- compute on v (R8-proven core) ----
        // Per-component argmax (strict > = first-max semantics).
        float mx = v[0].x, my = v[0].y;
        int ix = 0, iy = 0;
#pragma unroll
        for (int c = 1; c < NCH; c++) {
            if (v[c].x > mx) { mx = v[c].x; ix = c; }
            if (v[c].y > my) { my = v[c].y; iy = c; }
        }

        // s1 = sum e^(v-m), s2 = sum e^2(v-m), packed f32x2 pipe.
        unsigned long long m2, s1p, s2p;
        asm("mov.b64 %0, {%1, %2};" : "=l"(m2) : "f"(mx), "f"(my));
        asm("mov.b64 %0, {%1, %2};" : "=l"(s1p) : "f"(0.0f), "f"(0.0f));
        asm("mov.b64 %0, {%1, %2};" : "=l"(s2p) : "f"(0.0f), "f"(0.0f));
#pragma unroll
        for (int c = 0; c < NCH; c++) {
            unsigned long long v2c, d2, e2;
            asm("mov.b64 %0, {%1, %2};" : "=l"(v2c) : "f"(v[c].x), "f"(v[c].y));
            asm("sub.rn.f32x2 %0, %1, %2;" : "=l"(d2) : "l"(v2c), "l"(m2));
            float dx, dy;
            asm("mov.b64 {%0, %1}, %2;" : "=f"(dx), "=f"(dy) : "l"(d2));
            float ex = __expf(dx);
            float ey = __expf(dy);
            asm("mov.b64 %0, {%1, %2};" : "=l"(e2) : "f"(ex), "f"(ey));
            asm("add.rn.f32x2 %0, %1, %2;" : "=l"(s1p) : "l"(s1p), "l"(e2));
            asm("fma.rn.f32x2 %0, %1, %2, %3;" : "=l"(s2p) : "l"(e2), "l"(e2), "l"(s2p));
        }
        float s1x, s1y, s2x, s2y;
        asm("mov.b64 {%0, %1}, %2;" : "=f"(s1x), "=f"(s1y) : "l"(s1p));
        asm("mov.b64 {%0, %1}, %2;" : "=f"(s2x), "=f"(s2y) : "l"(s2p));

        atomicAdd(&s_sum[ix], __fdividef(s2x, s1x * s1x));
        atomicAdd(&s_sum[iy], __fdividef(s2y, s1y * s1y));
        atomicAdd(&s_cnt[ix], 1u);
        atomicAdd(&s_cnt[iy], 1u);

        // rotate pipeline
        q = qn;
#pragma unroll
        for (int c = 0; c < NCH; c++) v[c] = w[c];
    }

    __syncthreads();
    if (t < NCH) {
        atomicAdd(&g_sum[t], s_sum[t]);
        atomicAdd(&g_cnt[t], s_cnt[t]);
    }

    // ---- fused finalize: last block does the 19-term reduction ----
    __threadfence();
    __shared__ unsigned int s_last;
    if (t == 0) {
        unsigned int ticket = atomicAdd(&g_done, 1u);
        s_last = (ticket == GRID_BLOCKS - 1) ? 1u : 0u;
    }
    __syncthreads();
    if (s_last && t < 32) {
        int c = t;
        float partial = 0.0f;
        if (c < NCH) {
            float cnt   = (float)g_cnt[c];
            float scale = powf((float)NPIX, 1.0f - IW_F);        // Np^0.8
            float den   = fmaxf(powf(cnt, IW_F) * scale, 1.0f);  // max(hist^0.2*Np^0.8, 1)
            partial = g_sum[c] / den;
            g_sum[c] = 0.0f;                                     // reset for next replay
            g_cnt[c] = 0u;
        }
#pragma unroll
        for (int o = 16; o > 0; o >>= 1)
            partial += __shfl_down_sync(0xffffffffu, partial, o);
        if (c == 0) {
            out[0] = -partial / (float)(NBAT * NCH);
            g_done = 0;                                          // reset ticket
        }
    }
}

extern "C" void kernel_launch(void* const* d_in, const int* in_sizes, int n_in,
                              void* d_out, int out_size) {
    (void)in_sizes; (void)n_in; (void)out_size;
    const float2* x2 = (const float2*)d_in[0];
    float* out = (float*)d_out;

    // Single launch, one wave: 592 CTAs x 128 threads (4 CTAs/SM at <=128
    // regs). Register-double-buffered prefetch keeps ~78KB/SM of loads in
    // flight with no barriers. Finalize fused via the last-block ticket.
    msiw_kernel<<<GRID_BLOCKS, BLOCK_T>>>(x2, out);
}

// round 11
// speedup vs baseline: 1.0455x; 1.0455x over previous
#include <cuda_runtime.h>
#include <cuda_bf16.h>

// Problem constants: nw_out is [N=4, C=19, H=512, W=1024] float32.
#define NCH    19
#define NBAT   4
#define HH     512
#define WW     1024
#define HWP    (HH * WW)            // 524288 pixels per image
#define HWP2   (HWP / 2)            // 262144 float2 pairs per image-channel
#define NPIX   (NBAT * HWP)         // 2097152
#define NPAIR  (NPIX / 2)           // 1048576
#define IW_F   0.2f
#define BLOCK_T     128
#define GRID_BLOCKS 740             // 5 CTAs/SM x 148 SMs = one wave
#define STRIDE      (GRID_BLOCKS * BLOCK_T)   // 94720
#define DSTEPS      6               // 12 iterations covers NPAIR (11.07 needed)

// Scratch accumulators. Zeroed at module load; fused finalize re-zeroes them.
__device__ float        g_sum[NCH] = {};
__device__ unsigned int g_cnt[NCH] = {};
__device__ unsigned int g_done     = 0;

__device__ __forceinline__ void load_pairs(const float2* __restrict__ x2,
                                           int q, float2* __restrict__ v) {
    // Clamp keeps OOB threads on a valid (broadcast-cached) address.
    const int qc  = q < (NPAIR - 1) ? q : (NPAIR - 1);
    const int n   = qc / HWP2;
    const int hw2 = qc - n * HWP2;
    const float2* base = x2 + (size_t)n * (NCH * HWP2) + hw2;
#pragma unroll
    for (int c = 0; c < NCH; c++) v[c] = base[(size_t)c * HWP2];
}

__device__ __forceinline__ void compute_pairs(const float2* __restrict__ v,
                                              bool valid,
                                              float* __restrict__ s_sum,
                                              unsigned int* __restrict__ s_cnt) {
    // Per-component argmax (strict > = first-max semantics).
    float mx = v[0].x, my = v[0].y;
    int ix = 0, iy = 0;
#pragma unroll
    for (int c = 1; c < NCH; c++) {
        if (v[c].x > mx) { mx = v[c].x; ix = c; }
        if (v[c].y > my) { my = v[c].y; iy = c; }
    }

    // s1 = sum e^(v-m), s2 = sum e^2(v-m), packed f32x2 (R8-proven core).
    unsigned long long m2, s1p, s2p;
    asm("mov.b64 %0, {%1, %2};" : "=l"(m2) : "f"(mx), "f"(my));
    asm("mov.b64 %0, {%1, %2};" : "=l"(s1p) : "f"(0.0f), "f"(0.0f));
    asm("mov.b64 %0, {%1, %2};" : "=l"(s2p) : "f"(0.0f), "f"(0.0f));
#pragma unroll
    for (int c = 0; c < NCH; c++) {
        unsigned long long v2c, d2, e2;
        asm("mov.b64 %0, {%1, %2};" : "=l"(v2c) : "f"(v[c].x), "f"(v[c].y));
        asm("sub.rn.f32x2 %0, %1, %2;" : "=l"(d2) : "l"(v2c), "l"(m2));
        float dx, dy;
        asm("mov.b64 {%0, %1}, %2;" : "=f"(dx), "=f"(dy) : "l"(d2));
        float ex = __expf(dx);
        float ey = __expf(dy);
        asm("mov.b64 %0, {%1, %2};" : "=l"(e2) : "f"(ex), "f"(ey));
        asm("add.rn.f32x2 %0, %1, %2;" : "=l"(s1p) : "l"(s1p), "l"(e2));
        asm("fma.rn.f32x2 %0, %1, %2, %3;" : "=l"(s2p) : "l"(e2), "l"(e2), "l"(s2p));
    }
    float s1x, s1y, s2x, s2y;
    asm("mov.b64 {%0, %1}, %2;" : "=f"(s1x), "=f"(s1y) : "l"(s1p));
    asm("mov.b64 {%0, %1}, %2;" : "=f"(s2x), "=f"(s2y) : "l"(s2p));

    if (valid) {
        atomicAdd(&s_sum[ix], __fdividef(s2x, s1x * s1x));
        atomicAdd(&s_sum[iy], __fdividef(s2y, s1y * s1y));
        atomicAdd(&s_cnt[ix], 1u);
        atomicAdd(&s_cnt[iy], 1u);
    }
}

__global__ __launch_bounds__(BLOCK_T, 5) void msiw_kernel(const float2* __restrict__ x2,
                                                          float* __restrict__ out) {
    __shared__ float        s_sum[NCH];
    __shared__ unsigned int s_cnt[NCH];
    const int t = threadIdx.x;
    if (t < NCH) { s_sum[t] = 0.0f; s_cnt[t] = 0u; }
    __syncthreads();

    // Ping-pong software pipeline: A/B buffers alternate roles, NO copies.
    // Each buffer is loaded one phase before it is consumed, so its 19 LDG.64
    // are in flight across the other buffer's entire compute phase (loads and
    // compute overlap continuously; the scoreboard binds only at consumption).
    float2 A[NCH], B[NCH];
    int q = blockIdx.x * BLOCK_T + t;              // < STRIDE <= NPAIR

    load_pairs(x2, q, A);                          // prologue
#pragma unroll 1
    for (int s = 0; s < DSTEPS; s++) {
        const int q1 = q + STRIDE;
        load_pairs(x2, q1, B);                     // prefetch while computing A
        compute_pairs(A, q < NPAIR, s_sum, s_cnt);

        const int q2 = q1 + STRIDE;
        if (s < DSTEPS - 1)
            load_pairs(x2, q2, A);                 // prefetch while computing B
        compute_pairs(B, q1 < NPAIR, s_sum, s_cnt);
        q = q2;
    }

    __syncthreads();
    if (t < NCH) {
        atomicAdd(&g_sum[t], s_sum[t]);
        atomicAdd(&g_cnt[t], s_cnt[t]);
    }

    // ---- fused finalize: last block does the 19-term reduction ----
    __threadfence();
    __shared__ unsigned int s_last;
    if (t == 0) {
        unsigned int ticket = atomicAdd(&g_done, 1u);
        s_last = (ticket == GRID_BLOCKS - 1) ? 1u : 0u;
    }
    __syncthreads();
    if (s_last && t < 32) {
        int c = t;
        float partial = 0.0f;
        if (c < NCH) {
            float cnt   = (float)g_cnt[c];
            float scale = powf((float)NPIX, 1.0f - IW_F);        // Np^0.8
            float den   = fmaxf(powf(cnt, IW_F) * scale, 1.0f);  // max(hist^0.2*Np^0.8, 1)
            partial = g_sum[c] / den;
            g_sum[c] = 0.0f;                                     // reset for next replay
            g_cnt[c] = 0u;
        }
#pragma unroll
        for (int o = 16; o > 0; o >>= 1)
            partial += __shfl_down_sync(0xffffffffu, partial, o);
        if (c == 0) {
            out[0] = -partial / (float)(NBAT * NCH);
            g_done = 0;                                          // reset ticket
        }
    }
}

extern "C" void kernel_launch(void* const* d_in, const int* in_sizes, int n_in,
                              void* d_out, int out_size) {
    (void)in_sizes; (void)n_in; (void)out_size;
    const float2* x2 = (const float2*)d_in[0];
    float* out = (float*)d_out;

    // Single launch, one exact wave: 740 CTAs x 128 threads, 5 CTAs/SM.
    // Ping-pong register pipeline (no rotation copies) keeps ~97KB/SM of
    // loads continuously in flight. Finalize fused via last-block ticket.
    msiw_kernel<<<GRID_BLOCKS, BLOCK_T>>>(x2, out);
}

// round 12
// speedup vs baseline: 1.3197x; 1.2623x over previous
#include <cuda_runtime.h>
#include <cuda_bf16.h>

// Problem constants: nw_out is [N=4, C=19, H=512, W=1024] float32.
#define NCH    19
#define NBAT   4
#define HH     512
#define WW     1024
#define HWP    (HH * WW)            // 524288 pixels per image
#define HWP2   (HWP / 2)            // 262144 float2 pairs per image-channel
#define NPIX   (NBAT * HWP)         // 2097152
#define NPAIR  (NPIX / 2)           // 1048576
#define IW_F   0.2f
#define GRID_BLOCKS 740             // 5 CTAs/SM x 148 SMs = one wave

// Scratch accumulators. Zeroed at module load; fused finalize re-zeroes them.
__device__ float        g_sum[NCH] = {};
__device__ unsigned int g_cnt[NCH] = {};
__device__ unsigned int g_done     = 0;

__global__ __launch_bounds__(256, 5) void msiw_kernel(const float2* __restrict__ x2,
                                                      float* __restrict__ out) {
    __shared__ float        s_sum[NCH];
    __shared__ unsigned int s_cnt[NCH];
    if (threadIdx.x < NCH) {
        s_sum[threadIdx.x] = 0.0f;
        s_cnt[threadIdx.x] = 0u;
    }
    __syncthreads();

    const int stride = GRID_BLOCKS * 256;          // in float2 pairs
    for (int q = blockIdx.x * blockDim.x + threadIdx.x; q < NPAIR; q += stride) {
        const int n   = q / HWP2;                  // batch index
        const int hw2 = q - n * HWP2;              // pair position within image
        const float2* base = x2 + (size_t)n * (NCH * HWP2) + hw2;

        // Load all 19 channels as float2. The max-tree below consumes ALL v,
        // so ptxas front-batches the 19 LDG.64 (R3/R8-proven invariant).
        float2 v[NCH];
#pragma unroll
        for (int c = 0; c < NCH; c++) {
            v[c] = base[(size_t)c * HWP2];
        }

        // Max via FMNMX tree: depth 5 (~20 cyc) instead of the 220-cyc serial
        // compare-select chain. v[] dies at the subs right after -> next
        // iteration's loads can reuse those registers almost immediately.
        float tx[10], ty[10];
#pragma unroll
        for (int c = 0; c < 9; c++) {
            tx[c] = fmaxf(v[2 * c].x, v[2 * c + 1].x);
            ty[c] = fmaxf(v[2 * c].y, v[2 * c + 1].y);
        }
        tx[9] = v[18].x; ty[9] = v[18].y;
#pragma unroll
        for (int c = 0; c < 5; c++) {
            tx[c] = fmaxf(tx[c], tx[c + 5]);
            ty[c] = fmaxf(ty[c], ty[c + 5]);
        }
        tx[0] = fmaxf(tx[0], tx[3]); ty[0] = fmaxf(ty[0], ty[3]);
        tx[1] = fmaxf(tx[1], tx[4]); ty[1] = fmaxf(ty[1], ty[4]);
        const float mx = fmaxf(fmaxf(tx[0], tx[1]), tx[2]);
        const float my = fmaxf(fmaxf(ty[0], ty[1]), ty[2]);

        // s1 = sum e^(v-m), s2 = sum e^2(v-m), packed f32x2 core (R8-proven).
        // idx recovered from d==0 (FMNMX returns an input exactly; min-select
        // keeps first-max tie semantics). The idx chain only feeds the
        // fire-and-forget atomics, so its latency is off the critical path.
        unsigned long long m2, s1p, s2p;
        asm("mov.b64 %0, {%1, %2};" : "=l"(m2) : "f"(mx), "f"(my));
        asm("mov.b64 %0, {%1, %2};" : "=l"(s1p) : "f"(0.0f), "f"(0.0f));
        asm("mov.b64 %0, {%1, %2};" : "=l"(s2p) : "f"(0.0f), "f"(0.0f));
        int ix = 64, iy = 64;
#pragma unroll
        for (int c = 0; c < NCH; c++) {
            unsigned long long v2c, d2, e2;
            asm("mov.b64 %0, {%1, %2};" : "=l"(v2c) : "f"(v[c].x), "f"(v[c].y));
            asm("sub.rn.f32x2 %0, %1, %2;" : "=l"(d2) : "l"(v2c), "l"(m2));
            float dx, dy;
            asm("mov.b64 {%0, %1}, %2;" : "=f"(dx), "=f"(dy) : "l"(d2));
            ix = min(ix, (dx == 0.0f) ? c : 64);
            iy = min(iy, (dy == 0.0f) ? c : 64);
            float ex = __expf(dx);
            float ey = __expf(dy);
            asm("mov.b64 %0, {%1, %2};" : "=l"(e2) : "f"(ex), "f"(ey));
            asm("add.rn.f32x2 %0, %1, %2;" : "=l"(s1p) : "l"(s1p), "l"(e2));
            asm("fma.rn.f32x2 %0, %1, %2, %3;" : "=l"(s2p) : "l"(e2), "l"(e2), "l"(s2p));
        }
        float s1x, s1y, s2x, s2y;
        asm("mov.b64 {%0, %1}, %2;" : "=f"(s1x), "=f"(s1y) : "l"(s1p));
        asm("mov.b64 {%0, %1}, %2;" : "=f"(s2x), "=f"(s2y) : "l"(s2p));

        atomicAdd(&s_sum[ix], __fdividef(s2x, s1x * s1x));
        atomicAdd(&s_sum[iy], __fdividef(s2y, s1y * s1y));
        atomicAdd(&s_cnt[ix], 1u);
        atomicAdd(&s_cnt[iy], 1u);
    }

    __syncthreads();
    if (threadIdx.x < NCH) {
        atomicAdd(&g_sum[threadIdx.x], s_sum[threadIdx.x]);
        atomicAdd(&g_cnt[threadIdx.x], s_cnt[threadIdx.x]);
    }

    // ---- fused finalize: last block does the 19-term reduction ----
    __threadfence();
    __shared__ unsigned int s_last;
    if (threadIdx.x == 0) {
        unsigned int ticket = atomicAdd(&g_done, 1u);
        s_last = (ticket == GRID_BLOCKS - 1) ? 1u : 0u;
    }
    __syncthreads();
    if (s_last && threadIdx.x < 32) {
        int c = threadIdx.x;
        float partial = 0.0f;
        if (c < NCH) {
            float cnt   = (float)g_cnt[c];
            float scale = powf((float)NPIX, 1.0f - IW_F);        // Np^0.8
            float den   = fmaxf(powf(cnt, IW_F) * scale, 1.0f);  // max(hist^0.2*Np^0.8, 1)
            partial = g_sum[c] / den;
            g_sum[c] = 0.0f;                                     // reset for next replay
            g_cnt[c] = 0u;
        }
#pragma unroll
        for (int o = 16; o > 0; o >>= 1)
            partial += __shfl_down_sync(0xffffffffu, partial, o);
        if (c == 0) {
            out[0] = -partial / (float)(NBAT * NCH);
            g_done = 0;                                          // reset ticket
        }
    }
}

extern "C" void kernel_launch(void* const* d_in, const int* in_sizes, int n_in,
                              void* d_out, int out_size) {
    (void)in_sizes; (void)n_in; (void)out_size;
    const float2* x2 = (const float2*)d_in[0];
    float* out = (float*)d_out;

    // Single launch, one exact wave: 740 CTAs x 256 threads, 5 CTAs/SM.
    // R8 skeleton with the argmax critical path replaced by an FMNMX tree
    // (m in ~20 cyc) + off-critical-path idx recovery from d==0.
    msiw_kernel<<<GRID_BLOCKS, 256>>>(x2, out);
}